// round 6
// baseline (speedup 1.0000x reference)
#include <cuda_runtime.h>
#include <cuda_bf16.h>

// Problem constants
#define S_LEN 4096
#define BATCH 64
#define DIM   96
#define HID   128
#define ROWS  (S_LEN * BATCH)   // 262144

// ---------------------------------------------------------------------------
// Scratch (static device globals — allowed; no runtime allocation)
// ---------------------------------------------------------------------------
__device__ float g_P  [(size_t)ROWS * 1024];  // input projections (bias included), 1.07 GB
__device__ float g_ys0[(size_t)ROWS * 256];   // layer-0 output  [t][b][hf|hb]
__device__ float g_ys1[(size_t)ROWS * 256];   // layer-1 output
__device__ float g_W  [1024 * 256];           // packed Wih for current layer (max K=256)
__device__ float g_bias[1024];
__device__ int   g_flags[4 * S_LEN];          // [layer][cell][t] arrival counters

// ---------------------------------------------------------------------------
// Helpers
// ---------------------------------------------------------------------------
__device__ __forceinline__ float sigmoidf_(float x) {
    return 1.0f / (1.0f + __expf(-x));
}
// Accurate tanh built on __expf (robust even under -use_fast_math; no overflow)
__device__ __forceinline__ float tanh_acc(float x) {
    float ax = fabsf(x);
    float e  = __expf(-2.0f * ax);      // in (0,1]
    float t  = (1.0f - e) / (1.0f + e);
    return x < 0.0f ? -t : t;
}

// ---------------------------------------------------------------------------
// Kernel: zero per-step flags
// ---------------------------------------------------------------------------
__global__ void k_zero_flags() {
    int i = blockIdx.x * blockDim.x + threadIdx.x;
    if (i < 4 * S_LEN) g_flags[i] = 0;
}

// ---------------------------------------------------------------------------
// Kernel: pack [wih_f ; wih_b] -> g_W [1024,K], [b_f ; b_b] -> g_bias[1024]
// ---------------------------------------------------------------------------
__global__ void k_pack(const float* __restrict__ wf, const float* __restrict__ wb,
                       const float* __restrict__ bf, const float* __restrict__ bb,
                       int K) {
    int i = blockIdx.x * blockDim.x + threadIdx.x;
    int total = 1024 * K;
    if (i < total) {
        int n = i / K;
        int k = i - n * K;
        g_W[i] = (n < 512) ? wf[n * K + k] : wb[(n - 512) * K + k];
    }
    if (i < 1024) g_bias[i] = (i < 512) ? bf[i] : bb[i - 512];
}

// ---------------------------------------------------------------------------
// Kernel: GEMM  g_P[ROWS,1024] = A[ROWS,K] @ g_W[1024,K]^T + g_bias
// 128x128 tile, BK=16, 256 threads, 8x8 per thread.
// useYs0: 0 -> A = x (arg), 1 -> A = g_ys0
// ---------------------------------------------------------------------------
__global__ void __launch_bounds__(256)
k_gemm(const float* __restrict__ x, int useYs0, int K) {
    const float* __restrict__ A = useYs0 ? g_ys0 : x;

    __shared__ __align__(16) float As[16][132];
    __shared__ __align__(16) float Ws[16][132];

    const int tid = threadIdx.x;
    const int m0  = blockIdx.x * 128;
    const int n0  = blockIdx.y * 128;
    const int tx  = tid & 15;   // n direction
    const int ty  = tid >> 4;   // m direction

    const int lm = tid >> 2;          // 0..63
    const int lk = (tid & 3) << 2;    // 0,4,8,12

    float acc[8][8];
#pragma unroll
    for (int i = 0; i < 8; i++)
#pragma unroll
        for (int j = 0; j < 8; j++) acc[i][j] = 0.0f;

    for (int k0 = 0; k0 < K; k0 += 16) {
        float4 a0 = *(const float4*)&A[(size_t)(m0 + lm)      * K + k0 + lk];
        float4 a1 = *(const float4*)&A[(size_t)(m0 + lm + 64) * K + k0 + lk];
        float4 w0 = *(const float4*)&g_W[(size_t)(n0 + lm)      * K + k0 + lk];
        float4 w1 = *(const float4*)&g_W[(size_t)(n0 + lm + 64) * K + k0 + lk];

        __syncthreads();
        As[lk + 0][lm] = a0.x; As[lk + 1][lm] = a0.y;
        As[lk + 2][lm] = a0.z; As[lk + 3][lm] = a0.w;
        As[lk + 0][lm + 64] = a1.x; As[lk + 1][lm + 64] = a1.y;
        As[lk + 2][lm + 64] = a1.z; As[lk + 3][lm + 64] = a1.w;
        Ws[lk + 0][lm] = w0.x; Ws[lk + 1][lm] = w0.y;
        Ws[lk + 2][lm] = w0.z; Ws[lk + 3][lm] = w0.w;
        Ws[lk + 0][lm + 64] = w1.x; Ws[lk + 1][lm + 64] = w1.y;
        Ws[lk + 2][lm + 64] = w1.z; Ws[lk + 3][lm + 64] = w1.w;
        __syncthreads();

#pragma unroll
        for (int k = 0; k < 16; k++) {
            float a[8], w[8];
            *(float4*)&a[0] = *(const float4*)&As[k][ty * 8];
            *(float4*)&a[4] = *(const float4*)&As[k][ty * 8 + 4];
            *(float4*)&w[0] = *(const float4*)&Ws[k][tx * 8];
            *(float4*)&w[4] = *(const float4*)&Ws[k][tx * 8 + 4];
#pragma unroll
            for (int i = 0; i < 8; i++)
#pragma unroll
                for (int j = 0; j < 8; j++)
                    acc[i][j] = fmaf(a[i], w[j], acc[i][j]);
        }
    }

    float bsv[8];
#pragma unroll
    for (int j = 0; j < 8; j++) bsv[j] = g_bias[n0 + tx * 8 + j];

#pragma unroll
    for (int i = 0; i < 8; i++) {
        float* cptr = g_P + (size_t)(m0 + ty * 8 + i) * 1024 + n0 + tx * 8;
        float4 v0, v1;
        v0.x = acc[i][0] + bsv[0]; v0.y = acc[i][1] + bsv[1];
        v0.z = acc[i][2] + bsv[2]; v0.w = acc[i][3] + bsv[3];
        v1.x = acc[i][4] + bsv[4]; v1.y = acc[i][5] + bsv[5];
        v1.z = acc[i][6] + bsv[6]; v1.w = acc[i][7] + bsv[7];
        *(float4*)&cptr[0] = v0;
        *(float4*)&cptr[4] = v1;
    }
}

// ---------------------------------------------------------------------------
// Kernel: persistent recurrent layer (2 cells x 64 CTAs, 128 threads each).
// CTA (cell, g) owns hidden units j0 = 2g .. 2g+1.
// Thread (j = tid/64, b = tid%64) computes all 4 gates for unit (j0+j), batch b;
// carries c in a register; h is exchanged through the layer's ys buffer with
// per-step arrival counters (threadfence + atomicAdd / volatile poll).
// ---------------------------------------------------------------------------
__global__ void __launch_bounds__(128, 1)
k_recur(const float* __restrict__ whhf, const float* __restrict__ whhb, int layer) {
    __shared__ __align__(16) float h_s[64][132];
    __shared__ __align__(16) float w_s[8][132];

    const int tid  = threadIdx.x;
    const int cell = blockIdx.x >> 6;          // 0 = forward-cell, 1 = "backward"-cell
    const int j0   = (blockIdx.x & 63) * 2;

    const float* whh = cell ? whhb : whhf;
    float*       ys  = layer ? g_ys1 : g_ys0;
    int*         flag = g_flags + layer * (2 * S_LEN) + cell * S_LEN;
    const int pOff = cell * 512;               // cell's gate block inside g_P row
    const int hOff = cell * 128;               // cell's h block inside ys row

    // Load this CTA's 8 Whh rows (local row lr = j*4 + gate -> global row gate*128 + j0 + j)
    for (int idx = tid; idx < 8 * 128; idx += 128) {
        int lr = idx >> 7, k = idx & 127;
        int grow = ((lr & 3) * 128) + j0 + (lr >> 2);
        w_s[lr][k] = whh[grow * 128 + k];
    }
    __syncthreads();

    const int j = tid >> 6;      // 0..1 (local hidden unit)
    const int b = tid & 63;      // batch
    float c = 0.0f;

    for (int t = 0; t < S_LEN; t++) {
        if (t > 0) {
            if (tid == 0) {
                volatile int* vf = (volatile int*)&flag[t - 1];
                while (*vf < 64) __nanosleep(64);
            }
            __syncthreads();
            __threadfence();
            // Load full h[t-1] of this cell (64 x 128) into shared
            const float* hsrc = ys + (size_t)(t - 1) * BATCH * 256 + hOff;
            for (int idx = tid; idx < 64 * 32; idx += 128) {
                int rb = idx >> 5;
                int kc = (idx & 31) << 2;
                float4 v = __ldcg((const float4*)&hsrc[(size_t)rb * 256 + kc]);
                *(float4*)&h_s[rb][kc] = v;
            }
            __syncthreads();
        }

        // z init from precomputed input projection (+bias)
        const float* prow = g_P + ((size_t)t * BATCH + b) * 1024 + pOff + j0 + j;
        float zi = prow[0];
        float zf = prow[128];
        float zg = prow[256];
        float zo = prow[384];

        if (t > 0) {
            const float* wi = &w_s[j * 4 + 0][0];
            const float* wf = &w_s[j * 4 + 1][0];
            const float* wg = &w_s[j * 4 + 2][0];
            const float* wo = &w_s[j * 4 + 3][0];
#pragma unroll
            for (int k = 0; k < 128; k += 4) {
                float4 h4 = *(const float4*)&h_s[b][k];
                float4 vi = *(const float4*)&wi[k];
                float4 vf = *(const float4*)&wf[k];
                float4 vg = *(const float4*)&wg[k];
                float4 vo = *(const float4*)&wo[k];
                zi = fmaf(h4.x, vi.x, fmaf(h4.y, vi.y, fmaf(h4.z, vi.z, fmaf(h4.w, vi.w, zi))));
                zf = fmaf(h4.x, vf.x, fmaf(h4.y, vf.y, fmaf(h4.z, vf.z, fmaf(h4.w, vf.w, zf))));
                zg = fmaf(h4.x, vg.x, fmaf(h4.y, vg.y, fmaf(h4.z, vg.z, fmaf(h4.w, vg.w, zg))));
                zo = fmaf(h4.x, vo.x, fmaf(h4.y, vo.y, fmaf(h4.z, vo.z, fmaf(h4.w, vo.w, zo))));
            }
        }

        float si = sigmoidf_(zi);
        float sf = sigmoidf_(zf);
        float sg = tanh_acc(zg);
        float so = sigmoidf_(zo);
        c = fmaf(sf, c, si * sg);
        float h = so * tanh_acc(c);

        ys[((size_t)t * BATCH + b) * 256 + hOff + j0 + j] = h;

        __threadfence();
        __syncthreads();
        if (tid == 0) atomicAdd(&flag[t], 1);
    }
}

// ---------------------------------------------------------------------------
// Kernel: out = sigmoid(ys1 @ fc_w^T + fc_b).  One warp per row.
// ---------------------------------------------------------------------------
__global__ void __launch_bounds__(256)
k_fc(const float* __restrict__ fc_w, const float* __restrict__ fc_b,
     float* __restrict__ out) {
    int row  = blockIdx.x * 8 + (threadIdx.x >> 5);
    int lane = threadIdx.x & 31;
    const float* y = g_ys1 + (size_t)row * 256;
    float s = 0.0f;
#pragma unroll
    for (int k = lane; k < 256; k += 32) s = fmaf(y[k], fc_w[k], s);
#pragma unroll
    for (int off = 16; off > 0; off >>= 1)
        s += __shfl_xor_sync(0xffffffffu, s, off);
    if (lane == 0) out[row] = sigmoidf_(s + fc_b[0]);
}

// ---------------------------------------------------------------------------
// Host entry
// ---------------------------------------------------------------------------
extern "C" void kernel_launch(void* const* d_in, const int* in_sizes, int n_in,
                              void* d_out, int out_size) {
    const float* x     = (const float*)d_in[0];
    const float* wih0f = (const float*)d_in[1];
    const float* whh0f = (const float*)d_in[2];
    const float* b0f   = (const float*)d_in[3];
    const float* wih0b = (const float*)d_in[4];
    const float* whh0b = (const float*)d_in[5];
    const float* b0b   = (const float*)d_in[6];
    const float* wih1f = (const float*)d_in[7];
    const float* whh1f = (const float*)d_in[8];
    const float* b1f   = (const float*)d_in[9];
    const float* wih1b = (const float*)d_in[10];
    const float* whh1b = (const float*)d_in[11];
    const float* b1b   = (const float*)d_in[12];
    const float* fc_w  = (const float*)d_in[13];
    const float* fc_b  = (const float*)d_in[14];
    float* out = (float*)d_out;

    // 1) reset per-step flags (fresh every launch / graph replay)
    k_zero_flags<<<(4 * S_LEN + 255) / 256, 256>>>();

    // 2) layer 0 input projection: P = x @ [wih0f;wih0b]^T + bias
    k_pack<<<(1024 * 96 + 255) / 256, 256>>>(wih0f, wih0b, b0f, b0b, 96);
    k_gemm<<<dim3(ROWS / 128, 1024 / 128), 256>>>(x, 0, 96);

    // 3) layer 0 recurrence -> g_ys0
    k_recur<<<128, 128>>>(whh0f, whh0b, 0);

    // 4) layer 1 input projection: P = ys0 @ [wih1f;wih1b]^T + bias
    k_pack<<<(1024 * 256 + 255) / 256, 256>>>(wih1f, wih1b, b1f, b1b, 256);
    k_gemm<<<dim3(ROWS / 128, 1024 / 128), 256>>>(x /*unused*/, 1, 256);

    // 5) layer 1 recurrence -> g_ys1
    k_recur<<<128, 128>>>(whh1f, whh1b, 1);

    // 6) FC + sigmoid -> out [S*B]
    k_fc<<<ROWS / 8, 256>>>(fc_w, fc_b, out);
}

// round 7
// speedup vs baseline: 1.0404x; 1.0404x over previous
#include <cuda_runtime.h>
#include <cuda_bf16.h>

// Problem constants
#define S_LEN 4096
#define BATCH 64
#define DIM   96
#define HID   128
#define ROWS  (S_LEN * BATCH)   // 262144

// ---------------------------------------------------------------------------
// Scratch (static device globals — allowed; no runtime allocation)
// ---------------------------------------------------------------------------
__device__ float g_P  [(size_t)ROWS * 1024];  // input projections (bias included), 1.07 GB
__device__ float g_ys0[(size_t)ROWS * 256];   // layer-0 output  [t][b][hf|hb]
__device__ float g_ys1[(size_t)ROWS * 256];   // layer-1 output
__device__ float g_W  [1024 * 256];           // packed Wih for current layer (max K=256)
__device__ float g_bias[1024];
__device__ int   g_flags[4 * S_LEN];          // [layer][cell][t] arrival counters

// ---------------------------------------------------------------------------
// Helpers
// ---------------------------------------------------------------------------
__device__ __forceinline__ float sigmoidf_(float x) {
    return 1.0f / (1.0f + __expf(-x));
}
// Accurate tanh built on __expf (robust even under -use_fast_math; no overflow)
__device__ __forceinline__ float tanh_acc(float x) {
    float ax = fabsf(x);
    float e  = __expf(-2.0f * ax);      // in (0,1]
    float t  = (1.0f - e) / (1.0f + e);
    return x < 0.0f ? -t : t;
}

// ---------------------------------------------------------------------------
// Kernel: zero per-step flags
// ---------------------------------------------------------------------------
__global__ void k_zero_flags() {
    int i = blockIdx.x * blockDim.x + threadIdx.x;
    if (i < 4 * S_LEN) g_flags[i] = 0;
}

// ---------------------------------------------------------------------------
// Kernel: pack [wih_f ; wih_b] -> g_W [1024,K], [b_f ; b_b] -> g_bias[1024]
// ---------------------------------------------------------------------------
__global__ void k_pack(const float* __restrict__ wf, const float* __restrict__ wb,
                       const float* __restrict__ bf, const float* __restrict__ bb,
                       int K) {
    int i = blockIdx.x * blockDim.x + threadIdx.x;
    int total = 1024 * K;
    if (i < total) {
        int n = i / K;
        int k = i - n * K;
        g_W[i] = (n < 512) ? wf[n * K + k] : wb[(n - 512) * K + k];
    }
    if (i < 1024) g_bias[i] = (i < 512) ? bf[i] : bb[i - 512];
}

// ---------------------------------------------------------------------------
// Kernel: GEMM  g_P[ROWS,1024] = A[ROWS,K] @ g_W[1024,K]^T + g_bias
// 128x128 tile, BK=16, 256 threads, 8x8 per thread.
// useYs0: 0 -> A = x (arg), 1 -> A = g_ys0
// ---------------------------------------------------------------------------
__global__ void __launch_bounds__(256)
k_gemm(const float* __restrict__ x, int useYs0, int K) {
    const float* __restrict__ A = useYs0 ? g_ys0 : x;

    __shared__ __align__(16) float As[16][132];
    __shared__ __align__(16) float Ws[16][132];

    const int tid = threadIdx.x;
    const int m0  = blockIdx.x * 128;
    const int n0  = blockIdx.y * 128;
    const int tx  = tid & 15;   // n direction
    const int ty  = tid >> 4;   // m direction

    const int lm = tid >> 2;          // 0..63
    const int lk = (tid & 3) << 2;    // 0,4,8,12

    float acc[8][8];
#pragma unroll
    for (int i = 0; i < 8; i++)
#pragma unroll
        for (int j = 0; j < 8; j++) acc[i][j] = 0.0f;

    for (int k0 = 0; k0 < K; k0 += 16) {
        float4 a0 = *(const float4*)&A[(size_t)(m0 + lm)      * K + k0 + lk];
        float4 a1 = *(const float4*)&A[(size_t)(m0 + lm + 64) * K + k0 + lk];
        float4 w0 = *(const float4*)&g_W[(size_t)(n0 + lm)      * K + k0 + lk];
        float4 w1 = *(const float4*)&g_W[(size_t)(n0 + lm + 64) * K + k0 + lk];

        __syncthreads();
        As[lk + 0][lm] = a0.x; As[lk + 1][lm] = a0.y;
        As[lk + 2][lm] = a0.z; As[lk + 3][lm] = a0.w;
        As[lk + 0][lm + 64] = a1.x; As[lk + 1][lm + 64] = a1.y;
        As[lk + 2][lm + 64] = a1.z; As[lk + 3][lm + 64] = a1.w;
        Ws[lk + 0][lm] = w0.x; Ws[lk + 1][lm] = w0.y;
        Ws[lk + 2][lm] = w0.z; Ws[lk + 3][lm] = w0.w;
        Ws[lk + 0][lm + 64] = w1.x; Ws[lk + 1][lm + 64] = w1.y;
        Ws[lk + 2][lm + 64] = w1.z; Ws[lk + 3][lm + 64] = w1.w;
        __syncthreads();

#pragma unroll
        for (int k = 0; k < 16; k++) {
            float a[8], w[8];
            *(float4*)&a[0] = *(const float4*)&As[k][ty * 8];
            *(float4*)&a[4] = *(const float4*)&As[k][ty * 8 + 4];
            *(float4*)&w[0] = *(const float4*)&Ws[k][tx * 8];
            *(float4*)&w[4] = *(const float4*)&Ws[k][tx * 8 + 4];
#pragma unroll
            for (int i = 0; i < 8; i++)
#pragma unroll
                for (int j = 0; j < 8; j++)
                    acc[i][j] = fmaf(a[i], w[j], acc[i][j]);
        }
    }

    float bsv[8];
#pragma unroll
    for (int j = 0; j < 8; j++) bsv[j] = g_bias[n0 + tx * 8 + j];

#pragma unroll
    for (int i = 0; i < 8; i++) {
        float* cptr = g_P + (size_t)(m0 + ty * 8 + i) * 1024 + n0 + tx * 8;
        float4 v0, v1;
        v0.x = acc[i][0] + bsv[0]; v0.y = acc[i][1] + bsv[1];
        v0.z = acc[i][2] + bsv[2]; v0.w = acc[i][3] + bsv[3];
        v1.x = acc[i][4] + bsv[4]; v1.y = acc[i][5] + bsv[5];
        v1.z = acc[i][6] + bsv[6]; v1.w = acc[i][7] + bsv[7];
        *(float4*)&cptr[0] = v0;
        *(float4*)&cptr[4] = v1;
    }
}

// ---------------------------------------------------------------------------
// Kernel: persistent recurrent layer (2 cells x 64 CTAs, 128 threads each).
// CTA (cell, g) owns hidden units j0 = 2g .. 2g+1.
// Thread (j = tid/64, b = tid%64) computes all 4 gates for unit (j0+j), batch b;
// carries c in a register; h is exchanged through the layer's ys buffer with
// per-step arrival counters (threadfence + atomicAdd / volatile poll).
// ---------------------------------------------------------------------------
__global__ void __launch_bounds__(128, 1)
k_recur(const float* __restrict__ whhf, const float* __restrict__ whhb, int layer) {
    __shared__ __align__(16) float h_s[64][132];
    __shared__ __align__(16) float w_s[8][132];

    const int tid  = threadIdx.x;
    const int cell = blockIdx.x >> 6;          // 0 = forward-cell, 1 = "backward"-cell
    const int j0   = (blockIdx.x & 63) * 2;

    const float* whh = cell ? whhb : whhf;
    float*       ys  = layer ? g_ys1 : g_ys0;
    int*         flag = g_flags + layer * (2 * S_LEN) + cell * S_LEN;
    const int pOff = cell * 512;               // cell's gate block inside g_P row
    const int hOff = cell * 128;               // cell's h block inside ys row

    // Load this CTA's 8 Whh rows (local row lr = j*4 + gate -> global row gate*128 + j0 + j)
    for (int idx = tid; idx < 8 * 128; idx += 128) {
        int lr = idx >> 7, k = idx & 127;
        int grow = ((lr & 3) * 128) + j0 + (lr >> 2);
        w_s[lr][k] = whh[grow * 128 + k];
    }
    __syncthreads();

    const int j = tid >> 6;      // 0..1 (local hidden unit)
    const int b = tid & 63;      // batch
    float c = 0.0f;

    for (int t = 0; t < S_LEN; t++) {
        if (t > 0) {
            if (tid == 0) {
                volatile int* vf = (volatile int*)&flag[t - 1];
                while (*vf < 64) __nanosleep(64);
            }
            __syncthreads();
            __threadfence();
            // Load full h[t-1] of this cell (64 x 128) into shared
            const float* hsrc = ys + (size_t)(t - 1) * BATCH * 256 + hOff;
            for (int idx = tid; idx < 64 * 32; idx += 128) {
                int rb = idx >> 5;
                int kc = (idx & 31) << 2;
                float4 v = __ldcg((const float4*)&hsrc[(size_t)rb * 256 + kc]);
                *(float4*)&h_s[rb][kc] = v;
            }
            __syncthreads();
        }

        // z init from precomputed input projection (+bias)
        const float* prow = g_P + ((size_t)t * BATCH + b) * 1024 + pOff + j0 + j;
        float zi = prow[0];
        float zf = prow[128];
        float zg = prow[256];
        float zo = prow[384];

        if (t > 0) {
            const float* wi = &w_s[j * 4 + 0][0];
            const float* wf = &w_s[j * 4 + 1][0];
            const float* wg = &w_s[j * 4 + 2][0];
            const float* wo = &w_s[j * 4 + 3][0];
#pragma unroll
            for (int k = 0; k < 128; k += 4) {
                float4 h4 = *(const float4*)&h_s[b][k];
                float4 vi = *(const float4*)&wi[k];
                float4 vf = *(const float4*)&wf[k];
                float4 vg = *(const float4*)&wg[k];
                float4 vo = *(const float4*)&wo[k];
                zi = fmaf(h4.x, vi.x, fmaf(h4.y, vi.y, fmaf(h4.z, vi.z, fmaf(h4.w, vi.w, zi))));
                zf = fmaf(h4.x, vf.x, fmaf(h4.y, vf.y, fmaf(h4.z, vf.z, fmaf(h4.w, vf.w, zf))));
                zg = fmaf(h4.x, vg.x, fmaf(h4.y, vg.y, fmaf(h4.z, vg.z, fmaf(h4.w, vg.w, zg))));
                zo = fmaf(h4.x, vo.x, fmaf(h4.y, vo.y, fmaf(h4.z, vo.z, fmaf(h4.w, vo.w, zo))));
            }
        }

        float si = sigmoidf_(zi);
        float sf = sigmoidf_(zf);
        float sg = tanh_acc(zg);
        float so = sigmoidf_(zo);
        c = fmaf(sf, c, si * sg);
        float h = so * tanh_acc(c);

        ys[((size_t)t * BATCH + b) * 256 + hOff + j0 + j] = h;

        __threadfence();
        __syncthreads();
        if (tid == 0) atomicAdd(&flag[t], 1);
    }
}

// ---------------------------------------------------------------------------
// Kernel: out = sigmoid(ys1 @ fc_w^T + fc_b).  One warp per row.
// ---------------------------------------------------------------------------
__global__ void __launch_bounds__(256)
k_fc(const float* __restrict__ fc_w, const float* __restrict__ fc_b,
     float* __restrict__ out) {
    int row  = blockIdx.x * 8 + (threadIdx.x >> 5);
    int lane = threadIdx.x & 31;
    const float* y = g_ys1 + (size_t)row * 256;
    float s = 0.0f;
#pragma unroll
    for (int k = lane; k < 256; k += 32) s = fmaf(y[k], fc_w[k], s);
#pragma unroll
    for (int off = 16; off > 0; off >>= 1)
        s += __shfl_xor_sync(0xffffffffu, s, off);
    if (lane == 0) out[row] = sigmoidf_(s + fc_b[0]);
}

// ---------------------------------------------------------------------------
// Host entry
// ---------------------------------------------------------------------------
extern "C" void kernel_launch(void* const* d_in, const int* in_sizes, int n_in,
                              void* d_out, int out_size) {
    const float* x     = (const float*)d_in[0];
    const float* wih0f = (const float*)d_in[1];
    const float* whh0f = (const float*)d_in[2];
    const float* b0f   = (const float*)d_in[3];
    const float* wih0b = (const float*)d_in[4];
    const float* whh0b = (const float*)d_in[5];
    const float* b0b   = (const float*)d_in[6];
    const float* wih1f = (const float*)d_in[7];
    const float* whh1f = (const float*)d_in[8];
    const float* b1f   = (const float*)d_in[9];
    const float* wih1b = (const float*)d_in[10];
    const float* whh1b = (const float*)d_in[11];
    const float* b1b   = (const float*)d_in[12];
    const float* fc_w  = (const float*)d_in[13];
    const float* fc_b  = (const float*)d_in[14];
    float* out = (float*)d_out;

    // 1) reset per-step flags (fresh every launch / graph replay)
    k_zero_flags<<<(4 * S_LEN + 255) / 256, 256>>>();

    // 2) layer 0 input projection: P = x @ [wih0f;wih0b]^T + bias
    k_pack<<<(1024 * 96 + 255) / 256, 256>>>(wih0f, wih0b, b0f, b0b, 96);
    k_gemm<<<dim3(ROWS / 128, 1024 / 128), 256>>>(x, 0, 96);

    // 3) layer 0 recurrence -> g_ys0
    k_recur<<<128, 128>>>(whh0f, whh0b, 0);

    // 4) layer 1 input projection: P = ys0 @ [wih1f;wih1b]^T + bias
    k_pack<<<(1024 * 256 + 255) / 256, 256>>>(wih1f, wih1b, b1f, b1b, 256);
    k_gemm<<<dim3(ROWS / 128, 1024 / 128), 256>>>(x /*unused*/, 1, 256);

    // 5) layer 1 recurrence -> g_ys1
    k_recur<<<128, 128>>>(whh1f, whh1b, 1);

    // 6) FC + sigmoid -> out [S*B]
    k_fc<<<ROWS / 8, 256>>>(fc_w, fc_b, out);
}

// round 8
// speedup vs baseline: 1.4277x; 1.3723x over previous
#include <cuda_runtime.h>
#include <cuda_bf16.h>
#include <cstdint>

#define S_LEN 4096
#define BATCH 64
#define ROWS  (S_LEN * BATCH)   // 262144

typedef unsigned long long ull;
typedef uint32_t u32;

// ---------------------------------------------------------------------------
// Scratch (static device globals — no runtime allocation)
// ---------------------------------------------------------------------------
__device__ float g_P  [(size_t)1024 * ROWS];   // P_T[gate_row 0..1023][t*64+b]  (1.07 GB)
__device__ float g_ys0[(size_t)ROWS * 256];    // layer-0 output [row][hf|hb]
__device__ float g_ys1[(size_t)ROWS * 256];    // layer-1 output
__device__ float g_W  [1024 * 256];            // packed Wih for current layer
__device__ int   g_flags[2 * 2 * S_LEN * 64];  // [layer][cell][t][producer CTA]

// ---------------------------------------------------------------------------
// Helpers
// ---------------------------------------------------------------------------
__device__ __forceinline__ float sigmoidf_(float x) {
    return 1.0f / (1.0f + __expf(-x));
}
__device__ __forceinline__ float tanh_acc(float x) {
    float ax = fabsf(x);
    float e  = __expf(-2.0f * ax);
    float t  = (1.0f - e) / (1.0f + e);
    return x < 0.0f ? -t : t;
}
__device__ __forceinline__ void ffma2(ull& acc, ull a, ull b) {
    asm("fma.rn.f32x2 %0, %1, %2, %0;" : "+l"(acc) : "l"(a), "l"(b));
}
__device__ __forceinline__ ull pk2(float x, float y) {
    ull r; asm("mov.b64 %0, {%1, %2};" : "=l"(r) : "f"(x), "f"(y)); return r;
}
__device__ __forceinline__ float sum2(ull v) {
    float x, y; asm("mov.b64 {%0, %1}, %2;" : "=f"(x), "=f"(y) : "l"(v));
    return x + y;
}
__device__ __forceinline__ u32 f2tf32(float f) {
    u32 r; asm("cvt.rna.tf32.f32 %0, %1;" : "=r"(r) : "f"(f)); return r;
}
__device__ __forceinline__ void mma_tf32(float* c, const u32* a, const u32* b) {
    asm("mma.sync.aligned.m16n8k8.row.col.f32.tf32.tf32.f32 "
        "{%0,%1,%2,%3}, {%4,%5,%6,%7}, {%8,%9}, {%0,%1,%2,%3};"
        : "+f"(c[0]), "+f"(c[1]), "+f"(c[2]), "+f"(c[3])
        : "r"(a[0]), "r"(a[1]), "r"(a[2]), "r"(a[3]), "r"(b[0]), "r"(b[1]));
}

// ---------------------------------------------------------------------------
// zero per-step flags (2*2*4096*64 ints)
// ---------------------------------------------------------------------------
__global__ void k_zero_flags() {
    int i = blockIdx.x * blockDim.x + threadIdx.x;
    g_flags[i] = 0;
}

// ---------------------------------------------------------------------------
// pack [wih_f ; wih_b] -> g_W [1024][K]
// ---------------------------------------------------------------------------
__global__ void k_pack(const float* __restrict__ wf, const float* __restrict__ wb,
                       int K) {
    int i = blockIdx.x * blockDim.x + threadIdx.x;
    if (i < 1024 * K) {
        int n = i / K;
        int k = i - n * K;
        g_W[i] = (n < 512) ? wf[n * K + k] : wb[(n - 512) * K + k];
    }
}

// ---------------------------------------------------------------------------
// tf32 tensor-core GEMM:
//   g_P[n][row] = sum_k g_W[n][k] * A[row][k]   (NO bias; added in recurrence)
// Tile 128(n) x 128(row) x 32, 256 threads, 8 warps (2 M x 4 N),
// mma.m16n8k8.tf32, tiles pre-converted to tf32 in smem.
// grid = (8 n-tiles, 2048 row-tiles); x fastest -> row-tile L2 reuse.
// ---------------------------------------------------------------------------
__global__ void __launch_bounds__(256)
k_gemm(const float* __restrict__ x, int useYs0, int K) {
    const float* __restrict__ A = useYs0 ? g_ys0 : x;

    __shared__ __align__(16) u32 Ws[128][36];
    __shared__ __align__(16) u32 Xs[128][36];

    const int tid  = threadIdx.x;
    const int lane = tid & 31;
    const int warp = tid >> 5;
    const int wm   = warp & 1;      // 0..1 : 64-wide n slice
    const int wn   = warp >> 1;     // 0..3 : 32-wide row slice
    const int lr   = lane >> 2;     // 0..7
    const int lc   = lane & 3;      // 0..3

    const int n0 = blockIdx.x * 128;
    const int r0 = blockIdx.y * 128;

    float acc[4][4][4];
#pragma unroll
    for (int mi = 0; mi < 4; mi++)
#pragma unroll
        for (int ni = 0; ni < 4; ni++)
#pragma unroll
            for (int q = 0; q < 4; q++) acc[mi][ni][q] = 0.0f;

    for (int k0 = 0; k0 < K; k0 += 32) {
        __syncthreads();
        // g2s with fp32 -> tf32 conversion. 1024 float4 per tile, 4/thread.
#pragma unroll
        for (int p = 0; p < 4; p++) {
            int idx = tid + p * 256;        // 0..1023
            int r   = idx >> 3;             // 0..127
            int kc  = (idx & 7) << 2;       // 0..28
            float4 w4 = *(const float4*)&g_W[(size_t)(n0 + r) * K + k0 + kc];
            float4 a4 = *(const float4*)&A [(size_t)(r0 + r) * K + k0 + kc];
            u32 wq[4] = {f2tf32(w4.x), f2tf32(w4.y), f2tf32(w4.z), f2tf32(w4.w)};
            u32 aq[4] = {f2tf32(a4.x), f2tf32(a4.y), f2tf32(a4.z), f2tf32(a4.w)};
            *(uint4*)&Ws[r][kc] = *(uint4*)wq;
            *(uint4*)&Xs[r][kc] = *(uint4*)aq;
        }
        __syncthreads();

#pragma unroll
        for (int kk = 0; kk < 4; kk++) {
            int k8 = kk * 8;
            u32 afr[4][4], bfr[4][2];
#pragma unroll
            for (int mi = 0; mi < 4; mi++) {
                int mrow = wm * 64 + mi * 16 + lr;
                afr[mi][0] = Ws[mrow    ][k8     + lc];
                afr[mi][1] = Ws[mrow + 8][k8     + lc];
                afr[mi][2] = Ws[mrow    ][k8 + 4 + lc];
                afr[mi][3] = Ws[mrow + 8][k8 + 4 + lc];
            }
#pragma unroll
            for (int ni = 0; ni < 4; ni++) {
                int xrow = wn * 32 + ni * 8 + lr;
                bfr[ni][0] = Xs[xrow][k8     + lc];
                bfr[ni][1] = Xs[xrow][k8 + 4 + lc];
            }
#pragma unroll
            for (int mi = 0; mi < 4; mi++)
#pragma unroll
                for (int ni = 0; ni < 4; ni++)
                    mma_tf32(acc[mi][ni], afr[mi], bfr[ni]);
        }
    }

    // store transposed: P[n][row]
#pragma unroll
    for (int mi = 0; mi < 4; mi++) {
#pragma unroll
        for (int ni = 0; ni < 4; ni++) {
            int    ng = n0 + wm * 64 + mi * 16 + lr;
            size_t rg = (size_t)r0 + wn * 32 + ni * 8 + 2 * lc;
            float2 v0 = make_float2(acc[mi][ni][0], acc[mi][ni][1]);
            float2 v1 = make_float2(acc[mi][ni][2], acc[mi][ni][3]);
            *(float2*)&g_P[(size_t) ng      * ROWS + rg] = v0;
            *(float2*)&g_P[(size_t)(ng + 8) * ROWS + rg] = v1;
        }
    }
}

// ---------------------------------------------------------------------------
// persistent recurrent layer: 2 cells x 64 CTAs, 128 threads.
// CTA (cell, cidx) owns hidden units j0 = 2*cidx .. +1.
// Thread (j = tid/64, b = tid%64) computes 4 gates for unit j0+j, batch b.
// Sync: per-producer flag words (store-release pattern), no atomics.
// Matvec: fma.rn.f32x2 packed FMA; P prefetched before the poll.
// ---------------------------------------------------------------------------
__global__ void __launch_bounds__(128, 1)
k_recur(const float* __restrict__ whhf, const float* __restrict__ whhb,
        const float* __restrict__ biasf, const float* __restrict__ biasb,
        int layer) {
    __shared__ __align__(16) float h_s[64][132];
    __shared__ __align__(16) float w_s[8][132];

    const int tid  = threadIdx.x;
    const int cell = blockIdx.x >> 6;
    const int cidx = blockIdx.x & 63;
    const int j0   = cidx * 2;

    const float* whh  = cell ? whhb : whhf;
    const float* bias = cell ? biasb : biasf;
    float*       ys   = layer ? g_ys1 : g_ys0;
    int* flagBase = g_flags + (size_t)(layer * 2 + cell) * (S_LEN * 64);
    const int hOff = cell * 128;

    // Whh rows for this CTA: local row lr = j*4 + gate -> global row gate*128 + (j0+j)
    for (int idx = tid; idx < 8 * 128; idx += 128) {
        int lr = idx >> 7, k = idx & 127;
        int grow = ((lr & 3) * 128) + j0 + (lr >> 2);
        w_s[lr][k] = whh[grow * 128 + k];
    }

    const int j  = tid >> 6;
    const int b  = tid & 63;
    const int jr = j * 4;

    const float bi = bias[      j0 + j];
    const float bf = bias[128 + j0 + j];
    const float bg = bias[256 + j0 + j];
    const float bo = bias[384 + j0 + j];

    const float* pI = g_P + (size_t)(cell * 512 +       j0 + j) * ROWS;
    const float* pF = g_P + (size_t)(cell * 512 + 128 + j0 + j) * ROWS;
    const float* pG = g_P + (size_t)(cell * 512 + 256 + j0 + j) * ROWS;
    const float* pO = g_P + (size_t)(cell * 512 + 384 + j0 + j) * ROWS;

    __syncthreads();

    float c = 0.0f;
    for (int t = 0; t < S_LEN; t++) {
        const int row = t * 64 + b;

        // Prefetch input projections (independent of the recurrence) BEFORE poll
        float vi = __ldcg(pI + row) + bi;
        float vf = __ldcg(pF + row) + bf;
        float vg = __ldcg(pG + row) + bg;
        float vo = __ldcg(pO + row) + bo;

        if (t > 0) {
            // wait for all 64 producers of this cell at step t-1
            const int* fl = flagBase + (size_t)(t - 1) * 64;
            if (tid < 64) {
                volatile const int* vfp = fl + tid;
                while (*vfp == 0) __nanosleep(32);
            }
            __syncthreads();
            __threadfence();

            // load h[t-1] of this cell (64 x 128) into shared
            const float* hsrc = ys + (size_t)(t - 1) * 64 * 256 + hOff;
#pragma unroll
            for (int it = 0; it < 16; it++) {
                int idx = tid + it * 128;        // 0..2047 float4s
                int rb  = idx >> 5;
                int kc  = (idx & 31) << 2;
                float4 v = __ldcg((const float4*)(hsrc + (size_t)rb * 256 + kc));
                *(float4*)&h_s[rb][kc] = v;
            }
            __syncthreads();

            ull zi = pk2(vi, 0.0f), zf = pk2(vf, 0.0f);
            ull zg = pk2(vg, 0.0f), zo = pk2(vo, 0.0f);
#pragma unroll
            for (int k = 0; k < 128; k += 4) {
                ulonglong2 h2 = *(const ulonglong2*)&h_s[b][k];
                ulonglong2 w0 = *(const ulonglong2*)&w_s[jr + 0][k];
                ulonglong2 w1 = *(const ulonglong2*)&w_s[jr + 1][k];
                ulonglong2 w2 = *(const ulonglong2*)&w_s[jr + 2][k];
                ulonglong2 w3 = *(const ulonglong2*)&w_s[jr + 3][k];
                ffma2(zi, h2.x, w0.x); ffma2(zi, h2.y, w0.y);
                ffma2(zf, h2.x, w1.x); ffma2(zf, h2.y, w1.y);
                ffma2(zg, h2.x, w2.x); ffma2(zg, h2.y, w2.y);
                ffma2(zo, h2.x, w3.x); ffma2(zo, h2.y, w3.y);
            }
            vi = sum2(zi); vf = sum2(zf); vg = sum2(zg); vo = sum2(zo);
        }

        float si = sigmoidf_(vi);
        float sf = sigmoidf_(vf);
        float sg = tanh_acc(vg);
        float so = sigmoidf_(vo);
        c = fmaf(sf, c, si * sg);
        float h = so * tanh_acc(c);

        ys[(size_t)row * 256 + hOff + j0 + j] = h;

        __syncthreads();                 // all h stores of this CTA issued
        if (tid == 0) {
            __threadfence();             // make them visible GPU-wide
            *(volatile int*)(flagBase + (size_t)t * 64 + cidx) = 1;
        }
    }
}

// ---------------------------------------------------------------------------
// out = sigmoid(ys1 @ fc_w^T + fc_b). One warp per row.
// ---------------------------------------------------------------------------
__global__ void __launch_bounds__(256)
k_fc(const float* __restrict__ fc_w, const float* __restrict__ fc_b,
     float* __restrict__ out) {
    int row  = blockIdx.x * 8 + (threadIdx.x >> 5);
    int lane = threadIdx.x & 31;
    const float* y = g_ys1 + (size_t)row * 256;
    float s = 0.0f;
#pragma unroll
    for (int k = lane; k < 256; k += 32) s = fmaf(y[k], fc_w[k], s);
#pragma unroll
    for (int off = 16; off > 0; off >>= 1)
        s += __shfl_xor_sync(0xffffffffu, s, off);
    if (lane == 0) out[row] = sigmoidf_(s + fc_b[0]);
}

// ---------------------------------------------------------------------------
// Host entry
// ---------------------------------------------------------------------------
extern "C" void kernel_launch(void* const* d_in, const int* in_sizes, int n_in,
                              void* d_out, int out_size) {
    const float* x     = (const float*)d_in[0];
    const float* wih0f = (const float*)d_in[1];
    const float* whh0f = (const float*)d_in[2];
    const float* b0f   = (const float*)d_in[3];
    const float* wih0b = (const float*)d_in[4];
    const float* whh0b = (const float*)d_in[5];
    const float* b0b   = (const float*)d_in[6];
    const float* wih1f = (const float*)d_in[7];
    const float* whh1f = (const float*)d_in[8];
    const float* b1f   = (const float*)d_in[9];
    const float* wih1b = (const float*)d_in[10];
    const float* whh1b = (const float*)d_in[11];
    const float* b1b   = (const float*)d_in[12];
    const float* fc_w  = (const float*)d_in[13];
    const float* fc_b  = (const float*)d_in[14];
    float* out = (float*)d_out;

    // flags fresh every launch / graph replay
    k_zero_flags<<<(2 * 2 * S_LEN * 64) / 256, 256>>>();

    // layer 0: P_T = ([wih0f;wih0b] @ x^T), tf32 tensor cores
    k_pack<<<(1024 * 96 + 255) / 256, 256>>>(wih0f, wih0b, 96);
    k_gemm<<<dim3(8, ROWS / 128), 256>>>(x, 0, 96);
    k_recur<<<128, 128>>>(whh0f, whh0b, b0f, b0b, 0);

    // layer 1: P_T = ([wih1f;wih1b] @ ys0^T)
    k_pack<<<(1024 * 256 + 255) / 256, 256>>>(wih1f, wih1b, 256);
    k_gemm<<<dim3(8, ROWS / 128), 256>>>(x /*unused*/, 1, 256);
    k_recur<<<128, 128>>>(whh1f, whh1b, b1f, b1b, 1);

    // FC + sigmoid
    k_fc<<<ROWS / 8, 256>>>(fc_w, fc_b, out);
}

// round 9
// speedup vs baseline: 1.9239x; 1.3476x over previous
#include <cuda_runtime.h>
#include <cuda_bf16.h>
#include <cstdint>

#define S_LEN 4096
#define BATCH 64
#define ROWS  (S_LEN * BATCH)   // 262144

typedef unsigned long long ull;
typedef uint32_t u32;

// ---------------------------------------------------------------------------
// Scratch (static device globals — no runtime allocation)
// ---------------------------------------------------------------------------
__device__ float g_P  [(size_t)1024 * ROWS];   // P_T[gate_row 0..1023][t*64+b]  (1.07 GB)
__device__ float g_ys0[(size_t)ROWS * 256];    // layer-0 output [row][hf|hb]
__device__ float g_ys1[(size_t)ROWS * 256];    // layer-1 output
__device__ float g_W  [1024 * 256];            // packed Wih for current layer
__device__ int   g_flags[2 * 2 * S_LEN * 64];  // [layer][cell][t][producer CTA]

// ---------------------------------------------------------------------------
// Helpers
// ---------------------------------------------------------------------------
__device__ __forceinline__ float sigmoidf_(float x) {
    return 1.0f / (1.0f + __expf(-x));
}
__device__ __forceinline__ float tanha(float x) {          // HW MUFU.TANH
    float r; asm("tanh.approx.f32 %0, %1;" : "=f"(r) : "f"(x)); return r;
}
__device__ __forceinline__ float sigma(float x) {          // sigmoid via tanh
    return fmaf(tanha(0.5f * x), 0.5f, 0.5f);
}
__device__ __forceinline__ void ffma2(ull& acc, ull a, ull b) {
    asm("fma.rn.f32x2 %0, %1, %2, %0;" : "+l"(acc) : "l"(a), "l"(b));
}
__device__ __forceinline__ ull pk2(float x, float y) {
    ull r; asm("mov.b64 %0, {%1, %2};" : "=l"(r) : "f"(x), "f"(y)); return r;
}
__device__ __forceinline__ float sum2(ull v) {
    float x, y; asm("mov.b64 {%0, %1}, %2;" : "=f"(x), "=f"(y) : "l"(v));
    return x + y;
}
__device__ __forceinline__ u32 f2tf32(float f) {
    u32 r; asm("cvt.rna.tf32.f32 %0, %1;" : "=r"(r) : "f"(f)); return r;
}
__device__ __forceinline__ void mma_tf32(float* c, const u32* a, const u32* b) {
    asm("mma.sync.aligned.m16n8k8.row.col.f32.tf32.tf32.f32 "
        "{%0,%1,%2,%3}, {%4,%5,%6,%7}, {%8,%9}, {%0,%1,%2,%3};"
        : "+f"(c[0]), "+f"(c[1]), "+f"(c[2]), "+f"(c[3])
        : "r"(a[0]), "r"(a[1]), "r"(a[2]), "r"(a[3]), "r"(b[0]), "r"(b[1]));
}

// ---------------------------------------------------------------------------
// zero per-step flags
// ---------------------------------------------------------------------------
__global__ void k_zero_flags() {
    int i = blockIdx.x * blockDim.x + threadIdx.x;
    g_flags[i] = 0;
}

// ---------------------------------------------------------------------------
// pack [wih_f ; wih_b] -> g_W [1024][K]
// ---------------------------------------------------------------------------
__global__ void k_pack(const float* __restrict__ wf, const float* __restrict__ wb,
                       int K) {
    int i = blockIdx.x * blockDim.x + threadIdx.x;
    if (i < 1024 * K) {
        int n = i / K;
        int k = i - n * K;
        g_W[i] = (n < 512) ? wf[n * K + k] : wb[(n - 512) * K + k];
    }
}

// ---------------------------------------------------------------------------
// tf32 tensor-core GEMM: g_P[n][row] = sum_k g_W[n][k] * A[row][k]
// (unchanged from round 7 — verified correct)
// ---------------------------------------------------------------------------
__global__ void __launch_bounds__(256)
k_gemm(const float* __restrict__ x, int useYs0, int K) {
    const float* __restrict__ A = useYs0 ? g_ys0 : x;

    __shared__ __align__(16) u32 Ws[128][36];
    __shared__ __align__(16) u32 Xs[128][36];

    const int tid  = threadIdx.x;
    const int lane = tid & 31;
    const int warp = tid >> 5;
    const int wm   = warp & 1;
    const int wn   = warp >> 1;
    const int lr   = lane >> 2;
    const int lc   = lane & 3;

    const int n0 = blockIdx.x * 128;
    const int r0 = blockIdx.y * 128;

    float acc[4][4][4];
#pragma unroll
    for (int mi = 0; mi < 4; mi++)
#pragma unroll
        for (int ni = 0; ni < 4; ni++)
#pragma unroll
            for (int q = 0; q < 4; q++) acc[mi][ni][q] = 0.0f;

    for (int k0 = 0; k0 < K; k0 += 32) {
        __syncthreads();
#pragma unroll
        for (int p = 0; p < 4; p++) {
            int idx = tid + p * 256;
            int r   = idx >> 3;
            int kc  = (idx & 7) << 2;
            float4 w4 = *(const float4*)&g_W[(size_t)(n0 + r) * K + k0 + kc];
            float4 a4 = *(const float4*)&A [(size_t)(r0 + r) * K + k0 + kc];
            u32 wq[4] = {f2tf32(w4.x), f2tf32(w4.y), f2tf32(w4.z), f2tf32(w4.w)};
            u32 aq[4] = {f2tf32(a4.x), f2tf32(a4.y), f2tf32(a4.z), f2tf32(a4.w)};
            *(uint4*)&Ws[r][kc] = *(uint4*)wq;
            *(uint4*)&Xs[r][kc] = *(uint4*)aq;
        }
        __syncthreads();

#pragma unroll
        for (int kk = 0; kk < 4; kk++) {
            int k8 = kk * 8;
            u32 afr[4][4], bfr[4][2];
#pragma unroll
            for (int mi = 0; mi < 4; mi++) {
                int mrow = wm * 64 + mi * 16 + lr;
                afr[mi][0] = Ws[mrow    ][k8     + lc];
                afr[mi][1] = Ws[mrow + 8][k8     + lc];
                afr[mi][2] = Ws[mrow    ][k8 + 4 + lc];
                afr[mi][3] = Ws[mrow + 8][k8 + 4 + lc];
            }
#pragma unroll
            for (int ni = 0; ni < 4; ni++) {
                int xrow = wn * 32 + ni * 8 + lr;
                bfr[ni][0] = Xs[xrow][k8     + lc];
                bfr[ni][1] = Xs[xrow][k8 + 4 + lc];
            }
#pragma unroll
            for (int mi = 0; mi < 4; mi++)
#pragma unroll
                for (int ni = 0; ni < 4; ni++)
                    mma_tf32(acc[mi][ni], afr[mi], bfr[ni]);
        }
    }

#pragma unroll
    for (int mi = 0; mi < 4; mi++) {
#pragma unroll
        for (int ni = 0; ni < 4; ni++) {
            int    ng = n0 + wm * 64 + mi * 16 + lr;
            size_t rg = (size_t)r0 + wn * 32 + ni * 8 + 2 * lc;
            float2 v0 = make_float2(acc[mi][ni][0], acc[mi][ni][1]);
            float2 v1 = make_float2(acc[mi][ni][2], acc[mi][ni][3]);
            *(float2*)&g_P[(size_t) ng      * ROWS + rg] = v0;
            *(float2*)&g_P[(size_t)(ng + 8) * ROWS + rg] = v1;
        }
    }
}

// ---------------------------------------------------------------------------
// persistent recurrent layer: 2 cells x 64 CTAs, 128 threads.
// Sync: release store / acquire poll (no MEMBAR, no atomics, no nanosleep).
// h load split into two k-halves, second half overlapped with first FMA burst.
// Gates via HW tanh.approx.
// ---------------------------------------------------------------------------
__global__ void __launch_bounds__(128, 1)
k_recur(const float* __restrict__ whhf, const float* __restrict__ whhb,
        const float* __restrict__ biasf, const float* __restrict__ biasb,
        int layer) {
    __shared__ __align__(16) float h_s[64][132];
    __shared__ __align__(16) float w_s[8][132];

    const int tid  = threadIdx.x;
    const int cell = blockIdx.x >> 6;
    const int cidx = blockIdx.x & 63;
    const int j0   = cidx * 2;

    const float* whh  = cell ? whhb : whhf;
    const float* bias = cell ? biasb : biasf;
    float*       ys   = layer ? g_ys1 : g_ys0;
    int* flagBase = g_flags + (size_t)(layer * 2 + cell) * (S_LEN * 64);
    const int hOff = cell * 128;

    for (int idx = tid; idx < 8 * 128; idx += 128) {
        int lr = idx >> 7, k = idx & 127;
        int grow = ((lr & 3) * 128) + j0 + (lr >> 2);
        w_s[lr][k] = whh[grow * 128 + k];
    }

    const int j  = tid >> 6;
    const int b  = tid & 63;
    const int jr = j * 4;

    const float bi = bias[      j0 + j];
    const float bf = bias[128 + j0 + j];
    const float bg = bias[256 + j0 + j];
    const float bo = bias[384 + j0 + j];

    const float* pI = g_P + (size_t)(cell * 512 +       j0 + j) * ROWS;
    const float* pF = g_P + (size_t)(cell * 512 + 128 + j0 + j) * ROWS;
    const float* pG = g_P + (size_t)(cell * 512 + 256 + j0 + j) * ROWS;
    const float* pO = g_P + (size_t)(cell * 512 + 384 + j0 + j) * ROWS;

    __syncthreads();

    float c = 0.0f;
    for (int t = 0; t < S_LEN; t++) {
        const int row = t * 64 + b;

        // Prefetch input projections (DRAM latency hidden under the poll)
        float vi = __ldcg(pI + row) + bi;
        float vf = __ldcg(pF + row) + bf;
        float vg = __ldcg(pG + row) + bg;
        float vo = __ldcg(pO + row) + bo;

        if (t > 0) {
            // one warp polls all 64 producer flags (2 per lane, u64 acquire)
            if (tid < 32) {
                const ull* fp = (const ull*)(flagBase + (size_t)(t - 1) * 64) + tid;
                ull v;
                do {
                    asm volatile("ld.acquire.gpu.global.u64 %0, [%1];"
                                 : "=l"(v) : "l"(fp) : "memory");
                } while ((u32)v == 0u || (u32)(v >> 32) == 0u);
            }
            __syncthreads();

            const float* hsrc = ys + (size_t)(t - 1) * 64 * 256 + hOff;
            // issue half 0 (k 0..63) -> smem, and half 1 (k 64..127) -> regs
#pragma unroll
            for (int p = 0; p < 8; p++) {
                int idx = tid + p * 128;
                int rb  = idx >> 4;
                int kc  = (idx & 15) << 2;
                *(float4*)&h_s[rb][kc] =
                    __ldcg((const float4*)(hsrc + (size_t)rb * 256 + kc));
            }
            float4 buf[8];
#pragma unroll
            for (int p = 0; p < 8; p++) {
                int idx = tid + p * 128;
                int rb  = idx >> 4;
                int kc  = ((idx & 15) << 2) + 64;
                buf[p] = __ldcg((const float4*)(hsrc + (size_t)rb * 256 + kc));
            }
            __syncthreads();   // half 0 in smem

            ull zi = pk2(vi, 0.0f), zf = pk2(vf, 0.0f);
            ull zg = pk2(vg, 0.0f), zo = pk2(vo, 0.0f);
#pragma unroll
            for (int k = 0; k < 64; k += 4) {
                ulonglong2 h2 = *(const ulonglong2*)&h_s[b][k];
                ulonglong2 w0 = *(const ulonglong2*)&w_s[jr + 0][k];
                ulonglong2 w1 = *(const ulonglong2*)&w_s[jr + 1][k];
                ulonglong2 w2 = *(const ulonglong2*)&w_s[jr + 2][k];
                ulonglong2 w3 = *(const ulonglong2*)&w_s[jr + 3][k];
                ffma2(zi, h2.x, w0.x); ffma2(zi, h2.y, w0.y);
                ffma2(zf, h2.x, w1.x); ffma2(zf, h2.y, w1.y);
                ffma2(zg, h2.x, w2.x); ffma2(zg, h2.y, w2.y);
                ffma2(zo, h2.x, w3.x); ffma2(zo, h2.y, w3.y);
            }

            // half 1 regs -> smem (disjoint kc range; no race with half-0 reads)
#pragma unroll
            for (int p = 0; p < 8; p++) {
                int idx = tid + p * 128;
                int rb  = idx >> 4;
                int kc  = ((idx & 15) << 2) + 64;
                *(float4*)&h_s[rb][kc] = buf[p];
            }
            __syncthreads();

#pragma unroll
            for (int k = 64; k < 128; k += 4) {
                ulonglong2 h2 = *(const ulonglong2*)&h_s[b][k];
                ulonglong2 w0 = *(const ulonglong2*)&w_s[jr + 0][k];
                ulonglong2 w1 = *(const ulonglong2*)&w_s[jr + 1][k];
                ulonglong2 w2 = *(const ulonglong2*)&w_s[jr + 2][k];
                ulonglong2 w3 = *(const ulonglong2*)&w_s[jr + 3][k];
                ffma2(zi, h2.x, w0.x); ffma2(zi, h2.y, w0.y);
                ffma2(zf, h2.x, w1.x); ffma2(zf, h2.y, w1.y);
                ffma2(zg, h2.x, w2.x); ffma2(zg, h2.y, w2.y);
                ffma2(zo, h2.x, w3.x); ffma2(zo, h2.y, w3.y);
            }
            vi = sum2(zi); vf = sum2(zf); vg = sum2(zg); vo = sum2(zo);
        }

        float si = sigma(vi);
        float sf = sigma(vf);
        float sg = tanha(vg);
        float so = sigma(vo);
        c = fmaf(sf, c, si * sg);
        float h = so * tanha(c);

        ys[(size_t)row * 256 + hOff + j0 + j] = h;

        __syncthreads();   // all h stores of this CTA issued (CTA-scope order)
        if (tid == 0) {
            int* fa = flagBase + (size_t)t * 64 + cidx;
            asm volatile("st.release.gpu.global.u32 [%0], %1;"
                         :: "l"(fa), "r"(1) : "memory");
        }
    }
}

// ---------------------------------------------------------------------------
// out = sigmoid(ys1 @ fc_w^T + fc_b). One warp per row.
// ---------------------------------------------------------------------------
__global__ void __launch_bounds__(256)
k_fc(const float* __restrict__ fc_w, const float* __restrict__ fc_b,
     float* __restrict__ out) {
    int row  = blockIdx.x * 8 + (threadIdx.x >> 5);
    int lane = threadIdx.x & 31;
    const float* y = g_ys1 + (size_t)row * 256;
    float s = 0.0f;
#pragma unroll
    for (int k = lane; k < 256; k += 32) s = fmaf(y[k], fc_w[k], s);
#pragma unroll
    for (int off = 16; off > 0; off >>= 1)
        s += __shfl_xor_sync(0xffffffffu, s, off);
    if (lane == 0) out[row] = sigmoidf_(s + fc_b[0]);
}

// ---------------------------------------------------------------------------
// Host entry
// ---------------------------------------------------------------------------
extern "C" void kernel_launch(void* const* d_in, const int* in_sizes, int n_in,
                              void* d_out, int out_size) {
    const float* x     = (const float*)d_in[0];
    const float* wih0f = (const float*)d_in[1];
    const float* whh0f = (const float*)d_in[2];
    const float* b0f   = (const float*)d_in[3];
    const float* wih0b = (const float*)d_in[4];
    const float* whh0b = (const float*)d_in[5];
    const float* b0b   = (const float*)d_in[6];
    const float* wih1f = (const float*)d_in[7];
    const float* whh1f = (const float*)d_in[8];
    const float* b1f   = (const float*)d_in[9];
    const float* wih1b = (const float*)d_in[10];
    const float* whh1b = (const float*)d_in[11];
    const float* b1b   = (const float*)d_in[12];
    const float* fc_w  = (const float*)d_in[13];
    const float* fc_b  = (const float*)d_in[14];
    float* out = (float*)d_out;

    k_zero_flags<<<(2 * 2 * S_LEN * 64) / 256, 256>>>();

    k_pack<<<(1024 * 96 + 255) / 256, 256>>>(wih0f, wih0b, 96);
    k_gemm<<<dim3(8, ROWS / 128), 256>>>(x, 0, 96);
    k_recur<<<128, 128>>>(whh0f, whh0b, b0f, b0b, 0);

    k_pack<<<(1024 * 256 + 255) / 256, 256>>>(wih1f, wih1b, 256);
    k_gemm<<<dim3(8, ROWS / 128), 256>>>(x /*unused*/, 1, 256);
    k_recur<<<128, 128>>>(whh1f, whh1b, b1f, b1b, 1);

    k_fc<<<ROWS / 8, 256>>>(fc_w, fc_b, out);
}

// round 11
// speedup vs baseline: 4.3599x; 2.2661x over previous
#include <cuda_runtime.h>
#include <cuda_bf16.h>
#include <cstdint>

#define S_LEN 4096
#define BATCH 64
#define ROWS  (S_LEN * BATCH)   // 262144

#define KREG 64                  // k-values of Whh kept in registers
#define KSH  64                  // k-values of Whh kept in shared

typedef unsigned long long ull;
typedef uint32_t u32;

// ---------------------------------------------------------------------------
// Scratch (static device globals — no runtime allocation)
// ---------------------------------------------------------------------------
__device__ float g_P  [(size_t)ROWS * 1024];   // P[row][gate 0..1023]  (1.07 GB)
__device__ float g_ys0[(size_t)ROWS * 256];    // layer-0 output [row][hf|hb]
__device__ float g_ys1[(size_t)ROWS * 256];    // layer-1 output
__device__ float g_W  [1024 * 256];            // packed Wih for current layer

// ---------------------------------------------------------------------------
// Helpers
// ---------------------------------------------------------------------------
__device__ __forceinline__ float tanha(float x) {          // HW MUFU.TANH
    float r; asm("tanh.approx.f32 %0, %1;" : "=f"(r) : "f"(x)); return r;
}
__device__ __forceinline__ float sigma(float x) {          // sigmoid via tanh
    return fmaf(tanha(0.5f * x), 0.5f, 0.5f);
}
__device__ __forceinline__ void ffma2(ull& acc, ull a, ull b) {
    asm("fma.rn.f32x2 %0, %1, %2, %0;" : "+l"(acc) : "l"(a), "l"(b));
}
__device__ __forceinline__ ull add2(ull a, ull b) {
    ull r; asm("add.rn.f32x2 %0, %1, %2;" : "=l"(r) : "l"(a), "l"(b)); return r;
}
__device__ __forceinline__ ull pk2(float x, float y) {
    ull r; asm("mov.b64 %0, {%1, %2};" : "=l"(r) : "f"(x), "f"(y)); return r;
}
__device__ __forceinline__ void unpk2(ull v, float& x, float& y) {
    asm("mov.b64 {%0, %1}, %2;" : "=f"(x), "=f"(y) : "l"(v));
}
__device__ __forceinline__ u32 f2tf32(float f) {
    u32 r; asm("cvt.rna.tf32.f32 %0, %1;" : "=r"(r) : "f"(f)); return r;
}
__device__ __forceinline__ void mma_tf32(float* c, const u32* a, const u32* b) {
    asm("mma.sync.aligned.m16n8k8.row.col.f32.tf32.tf32.f32 "
        "{%0,%1,%2,%3}, {%4,%5,%6,%7}, {%8,%9}, {%0,%1,%2,%3};"
        : "+f"(c[0]), "+f"(c[1]), "+f"(c[2]), "+f"(c[3])
        : "r"(a[0]), "r"(a[1]), "r"(a[2]), "r"(a[3]), "r"(b[0]), "r"(b[1]));
}

// ---------------------------------------------------------------------------
// pack [wih_f ; wih_b] -> g_W [1024][K]
// ---------------------------------------------------------------------------
__global__ void k_pack(const float* __restrict__ wf, const float* __restrict__ wb,
                       int K) {
    int i = blockIdx.x * blockDim.x + threadIdx.x;
    if (i < 1024 * K) {
        int n = i / K;
        int k = i - n * K;
        g_W[i] = (n < 512) ? wf[n * K + k] : wb[(n - 512) * K + k];
    }
}

// ---------------------------------------------------------------------------
// tf32 tensor-core GEMM:  g_P[row][gate] = sum_k A[row][k] * g_W[gate][k]
// A-operand = rows (M), B-operand = gates (N).
// ---------------------------------------------------------------------------
__global__ void __launch_bounds__(256)
k_gemm(const float* __restrict__ x, int useYs0, int K) {
    const float* __restrict__ A = useYs0 ? g_ys0 : x;

    __shared__ __align__(16) u32 Ws[128][36];   // gate tile
    __shared__ __align__(16) u32 Xs[128][36];   // row tile

    const int tid  = threadIdx.x;
    const int lane = tid & 31;
    const int warp = tid >> 5;
    const int wm   = warp & 1;      // 64-row slice of M (rows)
    const int wn   = warp >> 1;     // 32-wide slice of N (gates)
    const int lr   = lane >> 2;
    const int lc   = lane & 3;

    const int n0 = blockIdx.x * 128;   // gates
    const int r0 = blockIdx.y * 128;   // rows

    float acc[4][4][4];
#pragma unroll
    for (int mi = 0; mi < 4; mi++)
#pragma unroll
        for (int ni = 0; ni < 4; ni++)
#pragma unroll
            for (int q = 0; q < 4; q++) acc[mi][ni][q] = 0.0f;

    for (int k0 = 0; k0 < K; k0 += 32) {
        __syncthreads();
#pragma unroll
        for (int p = 0; p < 4; p++) {
            int idx = tid + p * 256;
            int r   = idx >> 3;
            int kc  = (idx & 7) << 2;
            float4 w4 = *(const float4*)&g_W[(size_t)(n0 + r) * K + k0 + kc];
            float4 a4 = *(const float4*)&A [(size_t)(r0 + r) * K + k0 + kc];
            u32 wq[4] = {f2tf32(w4.x), f2tf32(w4.y), f2tf32(w4.z), f2tf32(w4.w)};
            u32 aq[4] = {f2tf32(a4.x), f2tf32(a4.y), f2tf32(a4.z), f2tf32(a4.w)};
            *(uint4*)&Ws[r][kc] = *(uint4*)wq;
            *(uint4*)&Xs[r][kc] = *(uint4*)aq;
        }
        __syncthreads();

#pragma unroll
        for (int kk = 0; kk < 4; kk++) {
            int k8 = kk * 8;
            u32 afr[4][4], bfr[4][2];
#pragma unroll
            for (int mi = 0; mi < 4; mi++) {           // A = rows
                int mrow = wm * 64 + mi * 16 + lr;
                afr[mi][0] = Xs[mrow    ][k8     + lc];
                afr[mi][1] = Xs[mrow + 8][k8     + lc];
                afr[mi][2] = Xs[mrow    ][k8 + 4 + lc];
                afr[mi][3] = Xs[mrow + 8][k8 + 4 + lc];
            }
#pragma unroll
            for (int ni = 0; ni < 4; ni++) {           // B = gates
                int grow = wn * 32 + ni * 8 + lr;
                bfr[ni][0] = Ws[grow][k8     + lc];
                bfr[ni][1] = Ws[grow][k8 + 4 + lc];
            }
#pragma unroll
            for (int mi = 0; mi < 4; mi++)
#pragma unroll
                for (int ni = 0; ni < 4; ni++)
                    mma_tf32(acc[mi][ni], afr[mi], bfr[ni]);
        }
    }

#pragma unroll
    for (int mi = 0; mi < 4; mi++) {
#pragma unroll
        for (int ni = 0; ni < 4; ni++) {
            size_t rowg = (size_t)r0 + wm * 64 + mi * 16 + lr;
            int    gg   = n0 + wn * 32 + ni * 8 + 2 * lc;
            *(float2*)&g_P[ rowg      * 1024 + gg] =
                make_float2(acc[mi][ni][0], acc[mi][ni][1]);
            *(float2*)&g_P[(rowg + 8) * 1024 + gg] =
                make_float2(acc[mi][ni][2], acc[mi][ni][3]);
        }
    }
}

// ---------------------------------------------------------------------------
// Batch-local recurrent layer: grid = 128 CTAs = (cell, batch), 256 threads.
// Thread t owns gate-rows 2t, 2t+1.  Whh: k<KREG in regs, rest in shared.
// Whole 4096-step chain is CTA-local (no inter-CTA sync).
// ---------------------------------------------------------------------------
__global__ void __launch_bounds__(256, 1)
k_recur2(const float* __restrict__ whhf, const float* __restrict__ whhb,
         const float* __restrict__ biasf, const float* __restrict__ biasb,
         int layer) {
    extern __shared__ __align__(16) char smem_raw[];
    ull*   w_p = (ull*)smem_raw;                                   // [KSH][256]
    ull*   h_d = (ull*)(smem_raw + (size_t)KSH * 256 * 8);         // [128]
    float* z_s = (float*)(smem_raw + (size_t)KSH * 256 * 8 + 1024);// [512]

    const int tid  = threadIdx.x;
    const int b    = blockIdx.x & 63;
    const int cell = blockIdx.x >> 6;

    const float* whh  = cell ? whhb : whhf;
    const float* bias = cell ? biasb : biasf;
    float*       ys   = layer ? g_ys1 : g_ys0;
    const int    hOff = cell * 128;

    const int r0 = 2 * tid, r1 = 2 * tid + 1;

    // Load Whh rows r0,r1: k<KREG into registers, rest into shared (pair-packed)
    ull wreg[KREG];
#pragma unroll
    for (int k4 = 0; k4 < 128; k4 += 4) {
        float4 a = *(const float4*)&whh[(size_t)r0 * 128 + k4];
        float4 c = *(const float4*)&whh[(size_t)r1 * 128 + k4];
        if (k4 < KREG) {
            wreg[k4 + 0] = pk2(a.x, c.x);
            wreg[k4 + 1] = pk2(a.y, c.y);
            wreg[k4 + 2] = pk2(a.z, c.z);
            wreg[k4 + 3] = pk2(a.w, c.w);
        } else {
            w_p[(k4 - KREG + 0) * 256 + tid] = pk2(a.x, c.x);
            w_p[(k4 - KREG + 1) * 256 + tid] = pk2(a.y, c.y);
            w_p[(k4 - KREG + 2) * 256 + tid] = pk2(a.z, c.z);
            w_p[(k4 - KREG + 3) * 256 + tid] = pk2(a.w, c.w);
        }
    }

    const float bb0 = bias[r0];
    const float bb1 = bias[r1];

    // P row layout: g_P[row][gate], row = t*64 + b  (b comes in via `row`;
    // pbase must NOT add b again — that was round 9's OOB bug)
    const float* pbase = g_P + (size_t)cell * 512 + r0;

    if (tid < 128) h_d[tid] = 0ull;     // h[-1] = 0 (dup pair)
    float c_state = 0.0f;
    __syncthreads();

#pragma unroll 1
    for (int t = 0; t < S_LEN; t++) {
        const size_t row = (size_t)t * 64 + b;

        // input projection for this step (independent of recurrence)
        float2 pv = __ldcg((const float2*)(pbase + row * 1024));

        // z(r0,r1) = Whh[r0/r1,:] . h  (packed row-pairs, 4 chains)
        ull a0 = 0, a1 = 0, a2 = 0, a3 = 0;
#pragma unroll
        for (int k = 0; k < KREG; k += 4) {
            ulonglong2 hA = *(const ulonglong2*)&h_d[k];
            ulonglong2 hB = *(const ulonglong2*)&h_d[k + 2];
            ffma2(a0, hA.x, wreg[k + 0]);
            ffma2(a1, hA.y, wreg[k + 1]);
            ffma2(a2, hB.x, wreg[k + 2]);
            ffma2(a3, hB.y, wreg[k + 3]);
        }
#pragma unroll
        for (int k = 0; k < KSH; k += 4) {
            ulonglong2 hA = *(const ulonglong2*)&h_d[KREG + k];
            ulonglong2 hB = *(const ulonglong2*)&h_d[KREG + k + 2];
            ffma2(a0, hA.x, w_p[(k + 0) * 256 + tid]);
            ffma2(a1, hA.y, w_p[(k + 1) * 256 + tid]);
            ffma2(a2, hB.x, w_p[(k + 2) * 256 + tid]);
            ffma2(a3, hB.y, w_p[(k + 3) * 256 + tid]);
        }
        ull s = add2(add2(a0, a1), add2(a2, a3));
        float z0, z1; unpk2(s, z0, z1);
        *(float2*)&z_s[r0] = make_float2(z0 + pv.x + bb0, z1 + pv.y + bb1);
        __syncthreads();

        if (tid < 128) {
            float zi = z_s[tid      ];
            float zf = z_s[tid + 128];
            float zg = z_s[tid + 256];
            float zo = z_s[tid + 384];
            float si = sigma(zi), sf = sigma(zf);
            float sg = tanha(zg), so = sigma(zo);
            c_state = fmaf(sf, c_state, si * sg);
            float h = so * tanha(c_state);
            h_d[tid] = pk2(h, h);
            ys[row * 256 + hOff + tid] = h;
        }
        __syncthreads();
    }
}

// ---------------------------------------------------------------------------
// out = sigmoid(ys1 @ fc_w^T + fc_b). One warp per row.
// ---------------------------------------------------------------------------
__global__ void __launch_bounds__(256)
k_fc(const float* __restrict__ fc_w, const float* __restrict__ fc_b,
     float* __restrict__ out) {
    int row  = blockIdx.x * 8 + (threadIdx.x >> 5);
    int lane = threadIdx.x & 31;
    const float* y = g_ys1 + (size_t)row * 256;
    float s = 0.0f;
#pragma unroll
    for (int k = lane; k < 256; k += 32) s = fmaf(y[k], fc_w[k], s);
#pragma unroll
    for (int off = 16; off > 0; off >>= 1)
        s += __shfl_xor_sync(0xffffffffu, s, off);
    if (lane == 0) out[row] = sigma(s + fc_b[0]);
}

// ---------------------------------------------------------------------------
// Host entry
// ---------------------------------------------------------------------------
extern "C" void kernel_launch(void* const* d_in, const int* in_sizes, int n_in,
                              void* d_out, int out_size) {
    const float* x     = (const float*)d_in[0];
    const float* wih0f = (const float*)d_in[1];
    const float* whh0f = (const float*)d_in[2];
    const float* b0f   = (const float*)d_in[3];
    const float* wih0b = (const float*)d_in[4];
    const float* whh0b = (const float*)d_in[5];
    const float* b0b   = (const float*)d_in[6];
    const float* wih1f = (const float*)d_in[7];
    const float* whh1f = (const float*)d_in[8];
    const float* b1f   = (const float*)d_in[9];
    const float* wih1b = (const float*)d_in[10];
    const float* whh1b = (const float*)d_in[11];
    const float* b1b   = (const float*)d_in[12];
    const float* fc_w  = (const float*)d_in[13];
    const float* fc_b  = (const float*)d_in[14];
    float* out = (float*)d_out;

    const int smemRec = KSH * 256 * 8 + 1024 + 512 * 4;   // 134,144 B
    cudaFuncSetAttribute(k_recur2,
                         cudaFuncAttributeMaxDynamicSharedMemorySize, smemRec);

    // layer 0
    k_pack<<<(1024 * 96 + 255) / 256, 256>>>(wih0f, wih0b, 96);
    k_gemm<<<dim3(8, ROWS / 128), 256>>>(x, 0, 96);
    k_recur2<<<128, 256, smemRec>>>(whh0f, whh0b, b0f, b0b, 0);

    // layer 1
    k_pack<<<(1024 * 256 + 255) / 256, 256>>>(wih1f, wih1b, 256);
    k_gemm<<<dim3(8, ROWS / 128), 256>>>(x /*unused*/, 1, 256);
    k_recur2<<<128, 256, smemRec>>>(whh1f, whh1b, b1f, b1b, 1);

    // FC + sigmoid
    k_fc<<<ROWS / 8, 256>>>(fc_w, fc_b, out);
}

// round 13
// speedup vs baseline: 5.6991x; 1.3072x over previous
#include <cuda_runtime.h>
#include <cuda_bf16.h>
#include <cstdint>

#define S_LEN 4096
#define BATCH 64
#define ROWS  (S_LEN * BATCH)   // 262144

typedef unsigned long long ull;
typedef uint32_t u32;

// ---------------------------------------------------------------------------
// Scratch (static device globals — no runtime allocation)
// ---------------------------------------------------------------------------
__device__ float g_P  [(size_t)ROWS * 1024];   // P[row][gate 0..1023]  (1.07 GB)
__device__ float g_ys0[(size_t)ROWS * 256];    // layer-0 output [row][hf|hb]
__device__ float g_ys1[(size_t)ROWS * 256];    // layer-1 output
__device__ float g_W  [1024 * 256];            // packed Wih for current layer

// ---------------------------------------------------------------------------
// Helpers
// ---------------------------------------------------------------------------
__device__ __forceinline__ float tanha(float x) {          // HW MUFU.TANH
    float r; asm("tanh.approx.f32 %0, %1;" : "=f"(r) : "f"(x)); return r;
}
__device__ __forceinline__ float sigma(float x) {          // sigmoid via tanh
    return fmaf(tanha(0.5f * x), 0.5f, 0.5f);
}
__device__ __forceinline__ void ffma2(ull& acc, ull a, ull b) {
    asm("fma.rn.f32x2 %0, %1, %2, %0;" : "+l"(acc) : "l"(a), "l"(b));
}
__device__ __forceinline__ float sum2(ull v) {
    float x, y; asm("mov.b64 {%0, %1}, %2;" : "=f"(x), "=f"(y) : "l"(v));
    return x + y;
}
__device__ __forceinline__ u32 bfpk(float lo, float hi) {  // bf16x2 {hi,lo}
    u32 r; asm("cvt.rn.bf16x2.f32 %0, %1, %2;" : "=r"(r) : "f"(hi), "f"(lo));
    return r;
}
__device__ __forceinline__ void mma_bf16(float* c, const u32* a, const u32* b) {
    asm("mma.sync.aligned.m16n8k16.row.col.f32.bf16.bf16.f32 "
        "{%0,%1,%2,%3}, {%4,%5,%6,%7}, {%8,%9}, {%0,%1,%2,%3};"
        : "+f"(c[0]), "+f"(c[1]), "+f"(c[2]), "+f"(c[3])
        : "r"(a[0]), "r"(a[1]), "r"(a[2]), "r"(a[3]), "r"(b[0]), "r"(b[1]));
}

// ---------------------------------------------------------------------------
// pack [wih_f ; wih_b] -> g_W [1024][K]
// ---------------------------------------------------------------------------
__global__ void k_pack(const float* __restrict__ wf, const float* __restrict__ wb,
                       int K) {
    int i = blockIdx.x * blockDim.x + threadIdx.x;
    if (i < 1024 * K) {
        int n = i / K;
        int k = i - n * K;
        g_W[i] = (n < 512) ? wf[n * K + k] : wb[(n - 512) * K + k];
    }
}

// ---------------------------------------------------------------------------
// bf16 tensor-core GEMM:  g_P[row][gate] = sum_k A[row][k] * g_W[gate][k]
// Tile 128(gate) x 128(row) x 32; mma.m16n8k16.bf16; fp32 accumulate.
// ---------------------------------------------------------------------------
__global__ void __launch_bounds__(256)
k_gemm(const float* __restrict__ x, int useYs0, int K) {
    const float* __restrict__ A = useYs0 ? g_ys0 : x;

    __shared__ __align__(16) u32 Ws[128][20];   // gate tile (bf16x2 along k)
    __shared__ __align__(16) u32 Xs[128][20];   // row tile

    const int tid  = threadIdx.x;
    const int lane = tid & 31;
    const int warp = tid >> 5;
    const int wm   = warp & 1;      // 64-row slice of M (rows)
    const int wn   = warp >> 1;     // 32-wide slice of N (gates)
    const int lr   = lane >> 2;
    const int lc   = lane & 3;

    const int n0 = blockIdx.x * 128;   // gates
    const int r0 = blockIdx.y * 128;   // rows

    float acc[4][4][4];
#pragma unroll
    for (int mi = 0; mi < 4; mi++)
#pragma unroll
        for (int ni = 0; ni < 4; ni++)
#pragma unroll
            for (int q = 0; q < 4; q++) acc[mi][ni][q] = 0.0f;

    for (int k0 = 0; k0 < K; k0 += 32) {
        __syncthreads();
        // g2s: 128 rows x 16 u32 per matrix = 512 uint4; 2 per thread
#pragma unroll
        for (int p = 0; p < 2; p++) {
            int idx = tid + p * 256;      // 0..511
            int r   = idx >> 2;           // 0..127
            int c4  = idx & 3;            // uint4 slot in row
            int kf  = c4 * 8;             // k offset (floats)
            float4 wa = *(const float4*)&g_W[(size_t)(n0 + r) * K + k0 + kf];
            float4 wb = *(const float4*)&g_W[(size_t)(n0 + r) * K + k0 + kf + 4];
            float4 aa = *(const float4*)&A [(size_t)(r0 + r) * K + k0 + kf];
            float4 ab = *(const float4*)&A [(size_t)(r0 + r) * K + k0 + kf + 4];
            uint4 wv = make_uint4(bfpk(wa.x, wa.y), bfpk(wa.z, wa.w),
                                  bfpk(wb.x, wb.y), bfpk(wb.z, wb.w));
            uint4 av = make_uint4(bfpk(aa.x, aa.y), bfpk(aa.z, aa.w),
                                  bfpk(ab.x, ab.y), bfpk(ab.z, ab.w));
            *(uint4*)&Ws[r][c4 * 4] = wv;
            *(uint4*)&Xs[r][c4 * 4] = av;
        }
        __syncthreads();

#pragma unroll
        for (int kk = 0; kk < 2; kk++) {       // 2 x k16 per 32-k chunk
            int k8 = kk * 8;
            u32 afr[4][4], bfr[4][2];
#pragma unroll
            for (int mi = 0; mi < 4; mi++) {   // A = rows
                int mrow = wm * 64 + mi * 16 + lr;
                afr[mi][0] = Xs[mrow    ][k8     + lc];
                afr[mi][1] = Xs[mrow + 8][k8     + lc];
                afr[mi][2] = Xs[mrow    ][k8 + 4 + lc];
                afr[mi][3] = Xs[mrow + 8][k8 + 4 + lc];
            }
#pragma unroll
            for (int ni = 0; ni < 4; ni++) {   // B = gates
                int grow = wn * 32 + ni * 8 + lr;
                bfr[ni][0] = Ws[grow][k8     + lc];
                bfr[ni][1] = Ws[grow][k8 + 4 + lc];
            }
#pragma unroll
            for (int mi = 0; mi < 4; mi++)
#pragma unroll
                for (int ni = 0; ni < 4; ni++)
                    mma_bf16(acc[mi][ni], afr[mi], bfr[ni]);
        }
    }

#pragma unroll
    for (int mi = 0; mi < 4; mi++) {
#pragma unroll
        for (int ni = 0; ni < 4; ni++) {
            size_t rowg = (size_t)r0 + wm * 64 + mi * 16 + lr;
            int    gg   = n0 + wn * 32 + ni * 8 + 2 * lc;
            *(float2*)&g_P[ rowg      * 1024 + gg] =
                make_float2(acc[mi][ni][0], acc[mi][ni][1]);
            *(float2*)&g_P[(rowg + 8) * 1024 + gg] =
                make_float2(acc[mi][ni][2], acc[mi][ni][3]);
        }
    }
}

// ---------------------------------------------------------------------------
// Batch-local recurrent layer: 128 CTAs = (cell, batch), 256 threads.
// Thread pair (u = tid>>1, half = tid&1): all 4 gate rows of hidden unit u,
// K range [half*64, half*64+64). Rows i,f in registers; rows g,o in smem.
// Partials combined via shfl.xor(1); both threads redundantly compute c,h.
// One barrier per step; h double-buffered in smem.
// ---------------------------------------------------------------------------
__global__ void __launch_bounds__(256, 1)
k_recur3(const float* __restrict__ whhf, const float* __restrict__ whhb,
         const float* __restrict__ biasf, const float* __restrict__ biasb,
         int layer) {
    extern __shared__ __align__(16) char smem_raw[];
    ulonglong2* wsm = (ulonglong2*)smem_raw;                 // [32][256] 128 KB
    float (*hbuf)[128] = (float(*)[128])(smem_raw + 131072); // [2][128]

    const int tid  = threadIdx.x;
    const int u    = tid >> 1;
    const int half = tid & 1;
    const int b    = blockIdx.x & 63;
    const int cell = blockIdx.x >> 6;

    const float* whh  = cell ? whhb : whhf;
    const float* bias = cell ? biasb : biasf;
    float*       ys   = layer ? g_ys1 : g_ys0;
    const int    hOff = cell * 128;
    const int    kb   = half * 64;

    // ---- weights: rows i,f -> regs (k-pair packed); rows g,o -> smem ----
    ull wi[32], wf_[32];
    {
        const ull* ri = (const ull*)(whh + (size_t)(u      ) * 128 + kb);
        const ull* rf = (const ull*)(whh + (size_t)(u + 128) * 128 + kb);
        const ulonglong2* rg = (const ulonglong2*)(whh + (size_t)(u + 256) * 128 + kb);
        const ulonglong2* ro = (const ulonglong2*)(whh + (size_t)(u + 384) * 128 + kb);
#pragma unroll
        for (int j = 0; j < 32; j++) { wi[j] = ri[j]; wf_[j] = rf[j]; }
#pragma unroll
        for (int q = 0; q < 16; q++) {
            wsm[       q * 256 + tid] = rg[q];
            wsm[(16 + q) * 256 + tid] = ro[q];
        }
    }

    // ---- bias + P pointers (half0: gates i,f ; half1: gates g,o) ----
    float bA, bB;
    const float *pA, *pB;
    if (half == 0) {
        bA = bias[u];       bB = bias[128 + u];
        pA = g_P + (size_t)b * 1024 + cell * 512 + u;
        pB = pA + 128;
    } else {
        bA = bias[256 + u]; bB = bias[384 + u];
        pA = g_P + (size_t)b * 1024 + cell * 512 + 256 + u;
        pB = pA + 128;
    }

    if (tid < 128) hbuf[0][tid] = 0.0f;   // h[-1] = 0
    float c_state = 0.0f;
    int p = 0;
    __syncthreads();

#pragma unroll 1
    for (int t = 0; t < S_LEN; t++) {
        // input projections (independent; LDG hides under matvec)
        float pvA = __ldcg(pA);
        float pvB = __ldcg(pB);
        pA += 65536; pB += 65536;         // next t: +64 rows * 1024

        const float* hb = &hbuf[p][kb];
        ull aI = 0, aF = 0, aG = 0, aO = 0;
#pragma unroll
        for (int q = 0; q < 16; q++) {
            ulonglong2 h2  = *(const ulonglong2*)&hb[4 * q];
            ulonglong2 wg2 = wsm[       q * 256 + tid];
            ulonglong2 wo2 = wsm[(16 + q) * 256 + tid];
            ffma2(aI, h2.x, wi [2 * q]);  ffma2(aI, h2.y, wi [2 * q + 1]);
            ffma2(aF, h2.x, wf_[2 * q]);  ffma2(aF, h2.y, wf_[2 * q + 1]);
            ffma2(aG, h2.x, wg2.x);       ffma2(aG, h2.y, wg2.y);
            ffma2(aO, h2.x, wo2.x);       ffma2(aO, h2.y, wo2.y);
        }

        float sI = sum2(aI), sF = sum2(aF), sG = sum2(aG), sO = sum2(aO);
        if (half == 0) { sI += pvA + bA; sF += pvB + bB; }
        else           { sG += pvA + bA; sO += pvB + bB; }

        // combine with partner (commutative adds -> bit-identical both sides)
        sI += __shfl_xor_sync(0xffffffffu, sI, 1);
        sF += __shfl_xor_sync(0xffffffffu, sF, 1);
        sG += __shfl_xor_sync(0xffffffffu, sG, 1);
        sO += __shfl_xor_sync(0xffffffffu, sO, 1);

        float si = sigma(sI), sf = sigma(sF);
        float sg = tanha(sG), so = sigma(sO);
        c_state = fmaf(sf, c_state, si * sg);
        float h = so * tanha(c_state);

        if (half == 0) hbuf[p ^ 1][u] = h;
        else           ys[((size_t)t * 64 + b) * 256 + hOff + u] = h;

        __syncthreads();
        p ^= 1;
    }
}

// ---------------------------------------------------------------------------
// out = sigmoid(ys1 @ fc_w^T + fc_b). One warp per row.
// ---------------------------------------------------------------------------
__global__ void __launch_bounds__(256)
k_fc(const float* __restrict__ fc_w, const float* __restrict__ fc_b,
     float* __restrict__ out) {
    int row  = blockIdx.x * 8 + (threadIdx.x >> 5);
    int lane = threadIdx.x & 31;
    const float* y = g_ys1 + (size_t)row * 256;
    float s = 0.0f;
#pragma unroll
    for (int k = lane; k < 256; k += 32) s = fmaf(y[k], fc_w[k], s);
#pragma unroll
    for (int off = 16; off > 0; off >>= 1)
        s += __shfl_xor_sync(0xffffffffu, s, off);
    if (lane == 0) out[row] = sigma(s + fc_b[0]);
}

// ---------------------------------------------------------------------------
// Host entry
// ---------------------------------------------------------------------------
extern "C" void kernel_launch(void* const* d_in, const int* in_sizes, int n_in,
                              void* d_out, int out_size) {
    const float* x     = (const float*)d_in[0];
    const float* wih0f = (const float*)d_in[1];
    const float* whh0f = (const float*)d_in[2];
    const float* b0f   = (const float*)d_in[3];
    const float* wih0b = (const float*)d_in[4];
    const float* whh0b = (const float*)d_in[5];
    const float* b0b   = (const float*)d_in[6];
    const float* wih1f = (const float*)d_in[7];
    const float* whh1f = (const float*)d_in[8];
    const float* b1f   = (const float*)d_in[9];
    const float* wih1b = (const float*)d_in[10];
    const float* whh1b = (const float*)d_in[11];
    const float* b1b   = (const float*)d_in[12];
    const float* fc_w  = (const float*)d_in[13];
    const float* fc_b  = (const float*)d_in[14];
    float* out = (float*)d_out;

    const int smemRec = 131072 + 2 * 128 * 4;   // 132,096 B
    cudaFuncSetAttribute(k_recur3,
                         cudaFuncAttributeMaxDynamicSharedMemorySize, smemRec);

    // layer 0
    k_pack<<<(1024 * 96 + 255) / 256, 256>>>(wih0f, wih0b, 96);
    k_gemm<<<dim3(8, ROWS / 128), 256>>>(x, 0, 96);
    k_recur3<<<128, 256, smemRec>>>(whh0f, whh0b, b0f, b0b, 0);

    // layer 1
    k_pack<<<(1024 * 256 + 255) / 256, 256>>>(wih1f, wih1b, 256);
    k_gemm<<<dim3(8, ROWS / 128), 256>>>(x /*unused*/, 1, 256);
    k_recur3<<<128, 256, smemRec>>>(whh1f, whh1b, b1f, b1b, 1);

    // FC + sigmoid
    k_fc<<<ROWS / 8, 256>>>(fc_w, fc_b, out);
}